// round 1
// baseline (speedup 1.0000x reference)
#include <cuda_runtime.h>

// Problem constants (fixed by the reference)
#define BG   128              // graphs
#define NN_  512              // nodes per graph
#define FF   128              // feature dim
#define DEG  16
#define ETOT (BG*NN_*DEG)     // 1,048,576 edges
#define NTOT (BG*NN_)         // 65,536 nodes
#define ADJ_WORDS (BG*NN_*(NN_/32))  // 1,048,576 uint32 = 4MB bitmask

// -------- device-global scratch (no allocations allowed) --------
__device__ unsigned int g_adj[ADJ_WORDS];
__device__ float g_dinv[NTOT];
__device__ float g_acc[(size_t)NTOT * FF];   // 32MB
__device__ float g_y[(size_t)NTOT * FF];     // 32MB

// ---------------- adjacency build ----------------
__global__ void clear_adj_kernel() {
    int i = blockIdx.x * blockDim.x + threadIdx.x;
    if (i < ADJ_WORDS) g_adj[i] = 0u;
}

__global__ void build_adj_kernel(const int* __restrict__ ei) {
    int e = blockIdx.x * blockDim.x + threadIdx.x;
    if (e >= ETOT) return;
    int src = ei[e];
    int dst = ei[ETOT + e];
    int g  = src >> 9;         // N = 512
    int si = src & 511;
    int di = dst & 511;
    atomicOr(&g_adj[(g * 512 + si) * 16 + (di >> 5)], 1u << (di & 31));
}

__global__ void dinv_kernel() {
    int i = blockIdx.x * blockDim.x + threadIdx.x;
    if (i >= NTOT) return;
    int deg = 0;
#pragma unroll
    for (int w = 0; w < 16; w++) deg += __popc(g_adj[i * 16 + w]);
    g_dinv[i] = (deg > 0) ? rsqrtf((float)deg) : 0.0f;
}

// ---------------- polynomial filter: acc = sum_{k=0..3} S^k x ----------------
// One CTA per (graph, 32-col feature slice). Everything stays in SMEM across hops.
// SMEM: adj bitmask 32KB + dinv 2KB + z 64KB + zhat 64KB = 162KB
#define FS 32
#define POLY_SMEM (8192*4 + 512*4 + 512*FS*4 + 512*FS*4)

__global__ void __launch_bounds__(512, 1) poly_kernel(const float* __restrict__ xin) {
    extern __shared__ unsigned int smraw[];
    unsigned int* adj_s = smraw;                     // 8192 words
    float* dinv_s = (float*)(smraw + 8192);          // 512
    float* z      = dinv_s + 512;                    // 512*32
    float* zh     = z + 512 * FS;                    // 512*32

    int g  = blockIdx.y;
    int fb = blockIdx.x * FS;
    int tid = threadIdx.x, w = tid >> 5, l = tid & 31;

    for (int i = tid; i < 8192; i += 512) adj_s[i] = g_adj[g * 8192 + i];
    if (tid < 512) dinv_s[tid] = g_dinv[g * 512 + tid];

    float acc[32];
    const float* xg = xin + ((size_t)g * 512) * FF + fb;
#pragma unroll
    for (int m = 0; m < 32; m++) {
        int n = w * 32 + m;
        float v = xg[(size_t)n * FF + l];
        acc[m] = v;
        z[n * FS + l] = v;
    }
    __syncthreads();

    for (int hop = 0; hop < 3; hop++) {
        // zhat = Dinv * z
#pragma unroll
        for (int m = 0; m < 32; m++) {
            int n = w * 32 + m;
            zh[n * FS + l] = dinv_s[n] * z[n * FS + l];
        }
        __syncthreads();
        // z_new[i] = dinv[i] * sum_{j in row(i)} zhat[j]
#pragma unroll 1
        for (int m = 0; m < 32; m++) {
            int n = w * 32 + m;
            float s = 0.0f;
            for (int wd = 0; wd < 16; wd++) {
                unsigned int bits = adj_s[n * 16 + wd];
                while (bits) {
                    int b = __ffs(bits) - 1;
                    bits &= bits - 1;
                    s += zh[(wd * 32 + b) * FS + l];
                }
            }
            float zn = dinv_s[n] * s;
            acc[m] += zn;
            z[n * FS + l] = zn;
        }
        __syncthreads();
    }

    float* yo = g_acc + ((size_t)g * 512) * FF + fb;
#pragma unroll
    for (int m = 0; m < 32; m++) {
        int n = w * 32 + m;
        yo[(size_t)n * FF + l] = acc[m];
    }
}

// ---------------- GEMM + bias + relu: Y = relu(g_acc @ W + b) ----------------
// CTA: 64 rows x 128 cols, 256 threads, each thread 4 rows x 8 cols.
#define GEMM_SMEM (16384*4 + 64*129*4)

__global__ void __launch_bounds__(256, 2) gemm_bias_relu_kernel(
        const float* __restrict__ W, const float* __restrict__ bias,
        float* __restrict__ Y) {
    extern __shared__ float sm[];
    float* Ws = sm;              // [128][128]
    float* As = sm + 16384;      // [64][129] padded

    int tid = threadIdx.x;
    size_t rowbase = (size_t)blockIdx.x * 64;

    for (int i = tid; i < 16384; i += 256) Ws[i] = W[i];
    for (int i = tid; i < 64 * 128; i += 256) {
        int r = i >> 7, k = i & 127;
        As[r * 129 + k] = g_acc[(rowbase + r) * 128 + k];
    }
    __syncthreads();

    int rg = tid >> 4;           // 0..15
    int cg = tid & 15;           // 0..15
    int c0 = cg * 8;

    float acc[4][8];
#pragma unroll
    for (int i = 0; i < 4; i++)
#pragma unroll
        for (int j = 0; j < 8; j++) acc[i][j] = 0.0f;

#pragma unroll 4
    for (int k = 0; k < 128; k++) {
        float a0 = As[(rg)      * 129 + k];
        float a1 = As[(rg + 16) * 129 + k];
        float a2 = As[(rg + 32) * 129 + k];
        float a3 = As[(rg + 48) * 129 + k];
        float4 w0 = *(const float4*)(Ws + k * 128 + c0);
        float4 w1 = *(const float4*)(Ws + k * 128 + c0 + 4);
        float wv[8] = {w0.x, w0.y, w0.z, w0.w, w1.x, w1.y, w1.z, w1.w};
#pragma unroll
        for (int j = 0; j < 8; j++) {
            acc[0][j] += a0 * wv[j];
            acc[1][j] += a1 * wv[j];
            acc[2][j] += a2 * wv[j];
            acc[3][j] += a3 * wv[j];
        }
    }

    float bv[8];
#pragma unroll
    for (int j = 0; j < 8; j++) bv[j] = bias[c0 + j];

#pragma unroll
    for (int i = 0; i < 4; i++) {
        size_t r = rowbase + rg + i * 16;
        float4 o0, o1;
        float t;
        t = acc[i][0] + bv[0]; o0.x = t > 0 ? t : 0;
        t = acc[i][1] + bv[1]; o0.y = t > 0 ? t : 0;
        t = acc[i][2] + bv[2]; o0.z = t > 0 ? t : 0;
        t = acc[i][3] + bv[3]; o0.w = t > 0 ? t : 0;
        t = acc[i][4] + bv[4]; o1.x = t > 0 ? t : 0;
        t = acc[i][5] + bv[5]; o1.y = t > 0 ? t : 0;
        t = acc[i][6] + bv[6]; o1.z = t > 0 ? t : 0;
        t = acc[i][7] + bv[7]; o1.w = t > 0 ? t : 0;
        *(float4*)(Y + r * 128 + c0)     = o0;
        *(float4*)(Y + r * 128 + c0 + 4) = o1;
    }
}

// ---------------- head: mean pool -> relu(h@Wr1+br1) -> h@Wr2+br2 ----------------
__global__ void __launch_bounds__(512) head_kernel(
        const float* __restrict__ Wr1, const float* __restrict__ br1,
        const float* __restrict__ Wr2, const float* __restrict__ br2,
        float* __restrict__ out) {
    __shared__ float part[4][128];
    __shared__ float hs[128];
    __shared__ float rs[64];
    int g = blockIdx.x;
    int tid = threadIdx.x;
    int f = tid & 127, q = tid >> 7;

    const float* yg = g_y + (size_t)g * 512 * 128;
    float s = 0.0f;
    for (int n = q * 128; n < q * 128 + 128; n++) s += yg[(size_t)n * 128 + f];
    part[q][f] = s;
    __syncthreads();

    if (tid < 128)
        hs[tid] = (part[0][tid] + part[1][tid] + part[2][tid] + part[3][tid]) * (1.0f / 512.0f);
    __syncthreads();

    if (tid < 64) {
        float a = br1[tid];
        for (int k = 0; k < 128; k++) a += hs[k] * Wr1[k * 64 + tid];
        rs[tid] = a > 0 ? a : 0;
    }
    __syncthreads();

    if (tid == 0) {
        float a = br2[0];
        for (int o = 0; o < 64; o++) a += rs[o] * Wr2[o];
        out[g] = a;
    }
}

// ---------------- launch ----------------
extern "C" void kernel_launch(void* const* d_in, const int* in_sizes, int n_in,
                              void* d_out, int out_size) {
    const float* X   = (const float*)d_in[0];
    const int*   ei  = (const int*)d_in[2];
    const float* W1  = (const float*)d_in[3];
    const float* b1  = (const float*)d_in[4];
    const float* W2  = (const float*)d_in[5];
    const float* b2  = (const float*)d_in[6];
    const float* Wr1 = (const float*)d_in[7];
    const float* br1 = (const float*)d_in[8];
    const float* Wr2 = (const float*)d_in[9];
    const float* br2 = (const float*)d_in[10];
    float* out = (float*)d_out;

    cudaFuncSetAttribute(poly_kernel, cudaFuncAttributeMaxDynamicSharedMemorySize, POLY_SMEM);
    cudaFuncSetAttribute(gemm_bias_relu_kernel, cudaFuncAttributeMaxDynamicSharedMemorySize, GEMM_SMEM);

    void* yaddr = nullptr;
    cudaGetSymbolAddress(&yaddr, g_y);
    float* Yp = (float*)yaddr;

    // adjacency (rebuilt every call; deterministic)
    clear_adj_kernel<<<ADJ_WORDS / 256, 256>>>();
    build_adj_kernel<<<ETOT / 256, 256>>>(ei);
    dinv_kernel<<<NTOT / 256, 256>>>();

    dim3 pgrid(FF / FS, BG);

    // layer 1
    poly_kernel<<<pgrid, 512, POLY_SMEM>>>(X);
    gemm_bias_relu_kernel<<<NTOT / 64, 256, GEMM_SMEM>>>(W1, b1, Yp);
    // layer 2
    poly_kernel<<<pgrid, 512, POLY_SMEM>>>(Yp);
    gemm_bias_relu_kernel<<<NTOT / 64, 256, GEMM_SMEM>>>(W2, b2, Yp);
    // head
    head_kernel<<<BG, 512>>>(Wr1, br1, Wr2, br2, out);
}

// round 2
// speedup vs baseline: 1.6587x; 1.6587x over previous
#include <cuda_runtime.h>

// Problem constants (fixed by the reference)
#define BG   128              // graphs
#define NN_  512              // nodes per graph
#define FF   128              // feature dim
#define DEG  16
#define ETOT (BG*NN_*DEG)     // 1,048,576 edges
#define NTOT (BG*NN_)         // 65,536 nodes
#define ADJ_WORDS (BG*NN_*(NN_/32))  // 4MB bitmask
#define PADN 64               // padded neighbor-list stride (max row degree ~ Poisson(16) tail)

// -------- device-global scratch (no allocations allowed) --------
__device__ unsigned int   g_adj[ADJ_WORDS];
__device__ unsigned short g_nbr[(size_t)NTOT * PADN];  // 8MB neighbor lists
__device__ short          g_cnt[NTOT];
__device__ float          g_dinv[NTOT];
__device__ float g_acc[(size_t)NTOT * FF];   // 32MB
__device__ float g_y[(size_t)NTOT * FF];     // 32MB

// ---------------- adjacency build ----------------
__global__ void clear_adj_kernel() {
    int i = blockIdx.x * blockDim.x + threadIdx.x;
    if (i < ADJ_WORDS) g_adj[i] = 0u;
}

__global__ void build_adj_kernel(const int* __restrict__ ei) {
    int e = blockIdx.x * blockDim.x + threadIdx.x;
    if (e >= ETOT) return;
    int src = ei[e];
    int dst = ei[ETOT + e];
    int g  = src >> 9;         // N = 512
    int si = src & 511;
    int di = dst & 511;
    atomicOr(&g_adj[(g * 512 + si) * 16 + (di >> 5)], 1u << (di & 31));
}

// Expand bitmask rows into padded uint16 neighbor lists + count + dinv.
__global__ void expand_kernel() {
    int i = blockIdx.x * blockDim.x + threadIdx.x;   // node id
    if (i >= NTOT) return;
    int cnt = 0;
    unsigned short* row = &g_nbr[(size_t)i * PADN];
#pragma unroll
    for (int w = 0; w < 16; w++) {
        unsigned int bits = g_adj[i * 16 + w];
        while (bits) {
            int b = __ffs(bits) - 1;
            bits &= bits - 1;
            if (cnt < PADN) row[cnt] = (unsigned short)(w * 32 + b);
            cnt++;
        }
    }
    if (cnt > PADN) cnt = PADN;
    g_cnt[i] = (short)cnt;
    g_dinv[i] = (cnt > 0) ? rsqrtf((float)cnt) : 0.0f;
}

// ---------------- polynomial filter: acc = sum_{k=0..3} S^k x ----------------
// One CTA per (graph, 32-col feature slice). u-space recurrence:
//   u_0 = dinv*x ; per hop: t = gather(u), z' = dinv*t (acc += z'), u' = dinv*z'
// SMEM: nbr 64KB + u buffers 2x64KB + dinv 2KB + cnt 1KB = ~195KB
#define FS 32
#define POLY_SMEM (NN_*PADN*2 + 2*NN_*FS*4 + NN_*4 + NN_*2)

__global__ void __launch_bounds__(512, 1) poly_kernel(const float* __restrict__ xin) {
    extern __shared__ unsigned char smraw[];
    unsigned short* nbr_s  = (unsigned short*)smraw;                 // 512*64 u16 = 64KB
    float* ubuf0           = (float*)(smraw + NN_*PADN*2);           // 64KB
    float* ubuf1           = ubuf0 + NN_ * FS;                       // 64KB
    float* dinv_s          = ubuf1 + NN_ * FS;                       // 2KB
    short* cnt_s           = (short*)(dinv_s + NN_);                 // 1KB

    int g  = blockIdx.y;
    int fb = blockIdx.x * FS;
    int tid = threadIdx.x, w = tid >> 5, l = tid & 31;

    // load neighbor lists (uint4 = 8 indices per load)
    {
        const uint4* src = (const uint4*)&g_nbr[(size_t)g * 512 * PADN];
        uint4* dst = (uint4*)nbr_s;
        for (int i = tid; i < 512 * PADN / 8; i += 512) dst[i] = src[i];
    }
    if (tid < 512) {
        dinv_s[tid] = g_dinv[g * 512 + tid];
        cnt_s[tid]  = g_cnt[g * 512 + tid];
    }

    float acc[32];
    const float* xg = xin + ((size_t)g * 512) * FF + fb;
#pragma unroll
    for (int m = 0; m < 32; m++) {
        int n = w * 32 + m;
        float v = xg[(size_t)n * FF + l];
        acc[m] = v;
    }
    __syncthreads();   // dinv_s ready
#pragma unroll
    for (int m = 0; m < 32; m++) {
        int n = w * 32 + m;
        ubuf0[n * FS + l] = dinv_s[n] * acc[m];
    }
    __syncthreads();

    float* ucur = ubuf0;
    float* unew = ubuf1;
#pragma unroll 1
    for (int hop = 0; hop < 3; hop++) {
#pragma unroll
        for (int m = 0; m < 32; m++) {
            int n = w * 32 + m;
            int cnt = cnt_s[n];
            const unsigned int* row = (const unsigned int*)&nbr_s[n * PADN];
            float s = 0.0f;
            int e = 0;
#pragma unroll 1
            for (; e + 2 <= cnt; e += 2) {
                unsigned int p = row[e >> 1];
                s += ucur[(p & 0xffffu) * FS + l];
                s += ucur[(p >> 16) * FS + l];
            }
            if (e < cnt) {
                unsigned int p = row[e >> 1];
                s += ucur[(p & 0xffffu) * FS + l];
            }
            float d  = dinv_s[n];
            float zn = d * s;
            acc[m] += zn;
            unew[n * FS + l] = d * zn;
        }
        __syncthreads();
        float* t = ucur; ucur = unew; unew = t;
    }

    float* yo = g_acc + ((size_t)g * 512) * FF + fb;
#pragma unroll
    for (int m = 0; m < 32; m++) {
        int n = w * 32 + m;
        yo[(size_t)n * FF + l] = acc[m];
    }
}

// ---------------- GEMM + bias + relu: Y = relu(g_acc @ W + b) ----------------
#define GEMM_SMEM (16384*4 + 64*129*4)

__global__ void __launch_bounds__(256, 2) gemm_bias_relu_kernel(
        const float* __restrict__ W, const float* __restrict__ bias,
        float* __restrict__ Y) {
    extern __shared__ float sm[];
    float* Ws = sm;              // [128][128]
    float* As = sm + 16384;      // [64][129] padded

    int tid = threadIdx.x;
    size_t rowbase = (size_t)blockIdx.x * 64;

    for (int i = tid; i < 16384; i += 256) Ws[i] = W[i];
    for (int i = tid; i < 64 * 128; i += 256) {
        int r = i >> 7, k = i & 127;
        As[r * 129 + k] = g_acc[(rowbase + r) * 128 + k];
    }
    __syncthreads();

    int rg = tid >> 4;           // 0..15
    int cg = tid & 15;           // 0..15
    int c0 = cg * 8;

    float acc[4][8];
#pragma unroll
    for (int i = 0; i < 4; i++)
#pragma unroll
        for (int j = 0; j < 8; j++) acc[i][j] = 0.0f;

#pragma unroll 4
    for (int k = 0; k < 128; k++) {
        float a0 = As[(rg)      * 129 + k];
        float a1 = As[(rg + 16) * 129 + k];
        float a2 = As[(rg + 32) * 129 + k];
        float a3 = As[(rg + 48) * 129 + k];
        float4 w0 = *(const float4*)(Ws + k * 128 + c0);
        float4 w1 = *(const float4*)(Ws + k * 128 + c0 + 4);
        float wv[8] = {w0.x, w0.y, w0.z, w0.w, w1.x, w1.y, w1.z, w1.w};
#pragma unroll
        for (int j = 0; j < 8; j++) {
            acc[0][j] += a0 * wv[j];
            acc[1][j] += a1 * wv[j];
            acc[2][j] += a2 * wv[j];
            acc[3][j] += a3 * wv[j];
        }
    }

    float bv[8];
#pragma unroll
    for (int j = 0; j < 8; j++) bv[j] = bias[c0 + j];

#pragma unroll
    for (int i = 0; i < 4; i++) {
        size_t r = rowbase + rg + i * 16;
        float4 o0, o1;
        float t;
        t = acc[i][0] + bv[0]; o0.x = t > 0 ? t : 0;
        t = acc[i][1] + bv[1]; o0.y = t > 0 ? t : 0;
        t = acc[i][2] + bv[2]; o0.z = t > 0 ? t : 0;
        t = acc[i][3] + bv[3]; o0.w = t > 0 ? t : 0;
        t = acc[i][4] + bv[4]; o1.x = t > 0 ? t : 0;
        t = acc[i][5] + bv[5]; o1.y = t > 0 ? t : 0;
        t = acc[i][6] + bv[6]; o1.z = t > 0 ? t : 0;
        t = acc[i][7] + bv[7]; o1.w = t > 0 ? t : 0;
        *(float4*)(Y + r * 128 + c0)     = o0;
        *(float4*)(Y + r * 128 + c0 + 4) = o1;
    }
}

// ---------------- head: mean pool -> relu(h@Wr1+br1) -> h@Wr2+br2 ----------------
__global__ void __launch_bounds__(512) head_kernel(
        const float* __restrict__ Wr1, const float* __restrict__ br1,
        const float* __restrict__ Wr2, const float* __restrict__ br2,
        float* __restrict__ out) {
    __shared__ float part[4][128];
    __shared__ float hs[128];
    __shared__ float rs[64];
    int g = blockIdx.x;
    int tid = threadIdx.x;
    int f = tid & 127, q = tid >> 7;

    const float* yg = g_y + (size_t)g * 512 * 128;
    float s = 0.0f;
    for (int n = q * 128; n < q * 128 + 128; n++) s += yg[(size_t)n * 128 + f];
    part[q][f] = s;
    __syncthreads();

    if (tid < 128)
        hs[tid] = (part[0][tid] + part[1][tid] + part[2][tid] + part[3][tid]) * (1.0f / 512.0f);
    __syncthreads();

    if (tid < 64) {
        float a = br1[tid];
        for (int k = 0; k < 128; k++) a += hs[k] * Wr1[k * 64 + tid];
        rs[tid] = a > 0 ? a : 0;
    }
    __syncthreads();

    if (tid == 0) {
        float a = br2[0];
        for (int o = 0; o < 64; o++) a += rs[o] * Wr2[o];
        out[g] = a;
    }
}

// ---------------- launch ----------------
extern "C" void kernel_launch(void* const* d_in, const int* in_sizes, int n_in,
                              void* d_out, int out_size) {
    const float* X   = (const float*)d_in[0];
    const int*   ei  = (const int*)d_in[2];
    const float* W1  = (const float*)d_in[3];
    const float* b1  = (const float*)d_in[4];
    const float* W2  = (const float*)d_in[5];
    const float* b2  = (const float*)d_in[6];
    const float* Wr1 = (const float*)d_in[7];
    const float* br1 = (const float*)d_in[8];
    const float* Wr2 = (const float*)d_in[9];
    const float* br2 = (const float*)d_in[10];
    float* out = (float*)d_out;

    cudaFuncSetAttribute(poly_kernel, cudaFuncAttributeMaxDynamicSharedMemorySize, POLY_SMEM);
    cudaFuncSetAttribute(gemm_bias_relu_kernel, cudaFuncAttributeMaxDynamicSharedMemorySize, GEMM_SMEM);

    void* yaddr = nullptr;
    cudaGetSymbolAddress(&yaddr, g_y);
    float* Yp = (float*)yaddr;

    // adjacency (rebuilt every call; deterministic)
    clear_adj_kernel<<<ADJ_WORDS / 256, 256>>>();
    build_adj_kernel<<<ETOT / 256, 256>>>(ei);
    expand_kernel<<<NTOT / 256, 256>>>();

    dim3 pgrid(FF / FS, BG);

    // layer 1
    poly_kernel<<<pgrid, 512, POLY_SMEM>>>(X);
    gemm_bias_relu_kernel<<<NTOT / 64, 256, GEMM_SMEM>>>(W1, b1, Yp);
    // layer 2
    poly_kernel<<<pgrid, 512, POLY_SMEM>>>(Yp);
    gemm_bias_relu_kernel<<<NTOT / 64, 256, GEMM_SMEM>>>(W2, b2, Yp);
    // head
    head_kernel<<<BG, 512>>>(Wr1, br1, Wr2, br2, out);
}

// round 3
// speedup vs baseline: 2.4200x; 1.4590x over previous
#include <cuda_runtime.h>

// Problem constants (fixed by the reference)
#define BG   128              // graphs
#define NN_  512              // nodes per graph
#define FF   128              // feature dim
#define DEG  16
#define ETOT (BG*NN_*DEG)     // 1,048,576 edges
#define NTOT (BG*NN_)         // 65,536 nodes
#define ADJ_WORDS (BG*NN_*(NN_/32))  // 4MB bitmask
#define PADN 64               // padded neighbor-list stride (multiple of 4)

// -------- device-global scratch (no allocations allowed) --------
__device__ unsigned int   g_adj[ADJ_WORDS];
__device__ unsigned short g_nbr[(size_t)NTOT * PADN];  // pre-scaled offsets (8B units)
__device__ short          g_cnt[NTOT];                  // padded to multiple of 4
__device__ float          g_dinv[NTOT];
__device__ float g_acc[(size_t)NTOT * FF];   // 32MB
__device__ float g_y[(size_t)NTOT * FF];     // 32MB

// ---------------- adjacency build ----------------
__global__ void clear_adj_kernel() {
    int i = blockIdx.x * blockDim.x + threadIdx.x;
    if (i < ADJ_WORDS) g_adj[i] = 0u;
}

__global__ void build_adj_kernel(const int* __restrict__ ei) {
    int e = blockIdx.x * blockDim.x + threadIdx.x;
    if (e >= ETOT) return;
    int src = ei[e];
    int dst = ei[ETOT + e];
    int g  = src >> 9;         // N = 512
    int si = src & 511;
    int di = dst & 511;
    atomicOr(&g_adj[(g * 512 + si) * 16 + (di >> 5)], 1u << (di & 31));
}

// Expand bitmask rows into padded u16 offset lists + padded count + dinv.
// Offset stored = (idx+1)*16 : 8-byte units into a u-buffer whose row 0 is zeros.
// Padding slots store 0 -> gather reads the zero row (adds 0.0f).
__global__ void expand_kernel() {
    int i = blockIdx.x * blockDim.x + threadIdx.x;   // node id
    if (i >= NTOT) return;
    int cnt = 0;
    unsigned short* row = &g_nbr[(size_t)i * PADN];
#pragma unroll
    for (int w = 0; w < 16; w++) {
        unsigned int bits = g_adj[i * 16 + w];
        while (bits) {
            int b = __ffs(bits) - 1;
            bits &= bits - 1;
            if (cnt < PADN) row[cnt] = (unsigned short)((w * 32 + b + 1) * 16);
            cnt++;
        }
    }
    if (cnt > PADN) cnt = PADN;
    g_dinv[i] = (cnt > 0) ? rsqrtf((float)cnt) : 0.0f;
    int cnt4 = (cnt + 3) & ~3;
    for (int e = cnt; e < cnt4; e++) row[e] = 0;   // zero-row padding
    g_cnt[i] = (short)cnt4;
}

// ---------------- packed f32x2 helpers ----------------
__device__ __forceinline__ void addx2(unsigned long long& a, unsigned long long b) {
    asm("add.rn.f32x2 %0, %0, %1;" : "+l"(a) : "l"(b));
}
__device__ __forceinline__ unsigned long long mulx2(unsigned long long a, unsigned long long b) {
    unsigned long long r;
    asm("mul.rn.f32x2 %0, %1, %2;" : "=l"(r) : "l"(a), "l"(b));
    return r;
}
__device__ __forceinline__ unsigned long long packx2(float lo, float hi) {
    unsigned long long r;
    asm("mov.b64 %0, {%1, %2};" : "=l"(r) : "f"(lo), "f"(hi));
    return r;
}

// ---------------- polynomial filter: acc = sum_{k=0..3} S^k x ----------------
// One CTA per (graph, 32-col feature slice). Each thread owns 2 adjacent cols
// (float2) of 16 nodes. u-space recurrence with a zero row at index 0:
//   u_0 = dinv*x ; per hop: s = gather(u), z' = dinv*s (acc += z'), u' = dinv*z'
// SMEM: nbr 64KB + 2 x (513 rows * 128B) u buffers + dinv 2KB + cnt 1KB ~ 196KB
#define FS 32
#define UROWS (NN_ + 1)
#define POLY_SMEM (NN_*PADN*2 + 2*UROWS*FS*4 + NN_*4 + NN_*2)

__global__ void __launch_bounds__(512, 1) poly_kernel(const float* __restrict__ xin) {
    extern __shared__ unsigned char smraw[];
    unsigned short* nbr_s = (unsigned short*)smraw;               // 64KB
    float* ubuf0          = (float*)(smraw + NN_*PADN*2);         // 513*32 floats
    float* ubuf1          = ubuf0 + UROWS * FS;
    float* dinv_s         = ubuf1 + UROWS * FS;                   // 512
    short* cnt_s          = (short*)(dinv_s + NN_);               // 512

    int g  = blockIdx.y;
    int fb = blockIdx.x * FS;
    int tid = threadIdx.x, w = tid >> 5, l = tid & 31;
    int h  = l >> 4;           // half-warp
    int l2 = l & 15;           // column pair index (cols 2*l2, 2*l2+1)
    int gbase = (w * 2 + h) * 16;   // first node of this thread's group

    // load neighbor offset lists (uint4 = 8 u16 per load)
    {
        const uint4* src = (const uint4*)&g_nbr[(size_t)g * 512 * PADN];
        uint4* dst = (uint4*)nbr_s;
        for (int i = tid; i < 512 * PADN / 8; i += 512) dst[i] = src[i];
    }
    if (tid < 512) {
        dinv_s[tid] = g_dinv[g * 512 + tid];
        cnt_s[tid]  = g_cnt[g * 512 + tid];
    }
    // zero row 0 of both u buffers
    if (tid < 32) ubuf0[tid] = 0.0f;
    else if (tid < 64) ubuf1[tid - 32] = 0.0f;
    __syncthreads();

    unsigned long long acc[16];
    const float* xg = xin + ((size_t)g * 512) * FF + fb + l2 * 2;
#pragma unroll
    for (int m = 0; m < 16; m++) {
        int n = gbase + m;
        float2 xv = *(const float2*)(xg + (size_t)n * FF);
        acc[m] = packx2(xv.x, xv.y);
        unsigned long long dd = packx2(dinv_s[n], dinv_s[n]);
        *(unsigned long long*)(ubuf0 + (n + 1) * FS + l2 * 2) = mulx2(acc[m], dd);
    }
    __syncthreads();

    float* ucur = ubuf0;
    float* unew = ubuf1;
#pragma unroll 1
    for (int hop = 0; hop < 3; hop++) {
        const char* ucb = (const char*)ucur + l2 * 8;   // per-thread gather base
#pragma unroll
        for (int m = 0; m < 16; m++) {
            int n = gbase + m;
            int cnt4 = cnt_s[n];
            const uint2* row = (const uint2*)&nbr_s[n * PADN];
            unsigned long long sa = 0ull, sb = 0ull;
#pragma unroll 1
            for (int e = 0; e < cnt4; e += 4) {
                uint2 p = row[e >> 2];
                unsigned int o0 = p.x & 0xffffu;
                unsigned int o1 = p.x >> 16;
                unsigned int o2 = p.y & 0xffffu;
                unsigned int o3 = p.y >> 16;
                unsigned long long v0 = *(const unsigned long long*)(ucb + (o0 << 3));
                unsigned long long v1 = *(const unsigned long long*)(ucb + (o1 << 3));
                unsigned long long v2 = *(const unsigned long long*)(ucb + (o2 << 3));
                unsigned long long v3 = *(const unsigned long long*)(ucb + (o3 << 3));
                addx2(sa, v0);
                addx2(sb, v1);
                addx2(sa, v2);
                addx2(sb, v3);
            }
            addx2(sa, sb);
            float d = dinv_s[n];
            unsigned long long dd = packx2(d, d);
            unsigned long long zn = mulx2(dd, sa);
            addx2(acc[m], zn);
            *(unsigned long long*)(unew + (n + 1) * FS + l2 * 2) = mulx2(dd, zn);
        }
        __syncthreads();
        float* t = ucur; ucur = unew; unew = t;
    }

    float* yo = g_acc + ((size_t)g * 512) * FF + fb + l2 * 2;
#pragma unroll
    for (int m = 0; m < 16; m++) {
        int n = gbase + m;
        *(unsigned long long*)(yo + (size_t)n * FF) = acc[m];
    }
}

// ---------------- GEMM + bias + relu: Y = relu(g_acc @ W + b) ----------------
#define GEMM_SMEM (16384*4 + 64*129*4)

__global__ void __launch_bounds__(256, 2) gemm_bias_relu_kernel(
        const float* __restrict__ W, const float* __restrict__ bias,
        float* __restrict__ Y) {
    extern __shared__ float sm[];
    float* Ws = sm;              // [128][128]
    float* As = sm + 16384;      // [64][129] padded

    int tid = threadIdx.x;
    size_t rowbase = (size_t)blockIdx.x * 64;

    for (int i = tid; i < 16384; i += 256) Ws[i] = W[i];
    for (int i = tid; i < 64 * 128; i += 256) {
        int r = i >> 7, k = i & 127;
        As[r * 129 + k] = g_acc[(rowbase + r) * 128 + k];
    }
    __syncthreads();

    int rg = tid >> 4;           // 0..15
    int cg = tid & 15;           // 0..15
    int c0 = cg * 8;

    float acc[4][8];
#pragma unroll
    for (int i = 0; i < 4; i++)
#pragma unroll
        for (int j = 0; j < 8; j++) acc[i][j] = 0.0f;

#pragma unroll 4
    for (int k = 0; k < 128; k++) {
        float a0 = As[(rg)      * 129 + k];
        float a1 = As[(rg + 16) * 129 + k];
        float a2 = As[(rg + 32) * 129 + k];
        float a3 = As[(rg + 48) * 129 + k];
        float4 w0 = *(const float4*)(Ws + k * 128 + c0);
        float4 w1 = *(const float4*)(Ws + k * 128 + c0 + 4);
        float wv[8] = {w0.x, w0.y, w0.z, w0.w, w1.x, w1.y, w1.z, w1.w};
#pragma unroll
        for (int j = 0; j < 8; j++) {
            acc[0][j] += a0 * wv[j];
            acc[1][j] += a1 * wv[j];
            acc[2][j] += a2 * wv[j];
            acc[3][j] += a3 * wv[j];
        }
    }

    float bv[8];
#pragma unroll
    for (int j = 0; j < 8; j++) bv[j] = bias[c0 + j];

#pragma unroll
    for (int i = 0; i < 4; i++) {
        size_t r = rowbase + rg + i * 16;
        float4 o0, o1;
        float t;
        t = acc[i][0] + bv[0]; o0.x = t > 0 ? t : 0;
        t = acc[i][1] + bv[1]; o0.y = t > 0 ? t : 0;
        t = acc[i][2] + bv[2]; o0.z = t > 0 ? t : 0;
        t = acc[i][3] + bv[3]; o0.w = t > 0 ? t : 0;
        t = acc[i][4] + bv[4]; o1.x = t > 0 ? t : 0;
        t = acc[i][5] + bv[5]; o1.y = t > 0 ? t : 0;
        t = acc[i][6] + bv[6]; o1.z = t > 0 ? t : 0;
        t = acc[i][7] + bv[7]; o1.w = t > 0 ? t : 0;
        *(float4*)(Y + r * 128 + c0)     = o0;
        *(float4*)(Y + r * 128 + c0 + 4) = o1;
    }
}

// ---------------- head: mean pool -> relu(h@Wr1+br1) -> h@Wr2+br2 ----------------
__global__ void __launch_bounds__(512) head_kernel(
        const float* __restrict__ Wr1, const float* __restrict__ br1,
        const float* __restrict__ Wr2, const float* __restrict__ br2,
        float* __restrict__ out) {
    __shared__ float part[4][128];
    __shared__ float hs[128];
    __shared__ float rs[64];
    int g = blockIdx.x;
    int tid = threadIdx.x;
    int f = tid & 127, q = tid >> 7;

    const float* yg = g_y + (size_t)g * 512 * 128;
    float s = 0.0f;
    for (int n = q * 128; n < q * 128 + 128; n++) s += yg[(size_t)n * 128 + f];
    part[q][f] = s;
    __syncthreads();

    if (tid < 128)
        hs[tid] = (part[0][tid] + part[1][tid] + part[2][tid] + part[3][tid]) * (1.0f / 512.0f);
    __syncthreads();

    if (tid < 64) {
        float a = br1[tid];
        for (int k = 0; k < 128; k++) a += hs[k] * Wr1[k * 64 + tid];
        rs[tid] = a > 0 ? a : 0;
    }
    __syncthreads();

    if (tid == 0) {
        float a = br2[0];
        for (int o = 0; o < 64; o++) a += rs[o] * Wr2[o];
        out[g] = a;
    }
}

// ---------------- launch ----------------
extern "C" void kernel_launch(void* const* d_in, const int* in_sizes, int n_in,
                              void* d_out, int out_size) {
    const float* X   = (const float*)d_in[0];
    const int*   ei  = (const int*)d_in[2];
    const float* W1  = (const float*)d_in[3];
    const float* b1  = (const float*)d_in[4];
    const float* W2  = (const float*)d_in[5];
    const float* b2  = (const float*)d_in[6];
    const float* Wr1 = (const float*)d_in[7];
    const float* br1 = (const float*)d_in[8];
    const float* Wr2 = (const float*)d_in[9];
    const float* br2 = (const float*)d_in[10];
    float* out = (float*)d_out;

    cudaFuncSetAttribute(poly_kernel, cudaFuncAttributeMaxDynamicSharedMemorySize, POLY_SMEM);
    cudaFuncSetAttribute(gemm_bias_relu_kernel, cudaFuncAttributeMaxDynamicSharedMemorySize, GEMM_SMEM);

    void* yaddr = nullptr;
    cudaGetSymbolAddress(&yaddr, g_y);
    float* Yp = (float*)yaddr;

    // adjacency (rebuilt every call; deterministic)
    clear_adj_kernel<<<ADJ_WORDS / 256, 256>>>();
    build_adj_kernel<<<ETOT / 256, 256>>>(ei);
    expand_kernel<<<NTOT / 256, 256>>>();

    dim3 pgrid(FF / FS, BG);

    // layer 1
    poly_kernel<<<pgrid, 512, POLY_SMEM>>>(X);
    gemm_bias_relu_kernel<<<NTOT / 64, 256, GEMM_SMEM>>>(W1, b1, Yp);
    // layer 2
    poly_kernel<<<pgrid, 512, POLY_SMEM>>>(Yp);
    gemm_bias_relu_kernel<<<NTOT / 64, 256, GEMM_SMEM>>>(W2, b2, Yp);
    // head
    head_kernel<<<BG, 512>>>(Wr1, br1, Wr2, br2, out);
}

// round 5
// speedup vs baseline: 3.1023x; 1.2819x over previous
#include <cuda_runtime.h>
#include <cuda_bf16.h>

// Problem constants (fixed by the reference)
#define BG   128              // graphs
#define NN_  512              // nodes per graph
#define FF   128              // feature dim
#define DEG  16
#define ETOT (BG*NN_*DEG)     // 1,048,576 edges
#define NTOT (BG*NN_)         // 65,536 nodes
#define ADJ_WORDS (BG*NN_*(NN_/32))  // 4MB bitmask
#define PADN 64               // padded neighbor-list stride (multiple of 4)

// -------- device-global scratch (no allocations allowed) --------
__device__ unsigned int   g_adj[ADJ_WORDS];
__device__ unsigned short g_nbr[(size_t)NTOT * PADN];  // pre-scaled offsets (8B units)
__device__ short          g_cnt[NTOT];                  // padded to multiple of 4
__device__ float          g_dinv[NTOT];
__device__ float g_acc[(size_t)NTOT * FF];   // 32MB
__device__ float g_y[(size_t)NTOT * FF];     // 32MB
__device__ unsigned int g_wt1[16384];        // W1^T split: [0,8192) hi pairs, [8192,16384) lo pairs
__device__ unsigned int g_wt2[16384];        // W2^T split

// ---------------- adjacency build ----------------
__global__ void clear_adj_kernel() {
    int i = blockIdx.x * blockDim.x + threadIdx.x;
    if (i < ADJ_WORDS) g_adj[i] = 0u;
}

__global__ void build_adj_kernel(const int* __restrict__ ei) {
    int e = blockIdx.x * blockDim.x + threadIdx.x;
    if (e >= ETOT) return;
    int src = ei[e];
    int dst = ei[ETOT + e];
    int g  = src >> 9;         // N = 512
    int si = src & 511;
    int di = dst & 511;
    atomicOr(&g_adj[(g * 512 + si) * 16 + (di >> 5)], 1u << (di & 31));
}

// Expand bitmask rows into padded u16 offset lists + padded count + dinv.
__global__ void expand_kernel() {
    int i = blockIdx.x * blockDim.x + threadIdx.x;   // node id
    if (i >= NTOT) return;
    int cnt = 0;
    unsigned short* row = &g_nbr[(size_t)i * PADN];
#pragma unroll
    for (int w = 0; w < 16; w++) {
        unsigned int bits = g_adj[i * 16 + w];
        while (bits) {
            int b = __ffs(bits) - 1;
            bits &= bits - 1;
            if (cnt < PADN) row[cnt] = (unsigned short)((w * 32 + b + 1) * 16);
            cnt++;
        }
    }
    if (cnt > PADN) cnt = PADN;
    g_dinv[i] = (cnt > 0) ? rsqrtf((float)cnt) : 0.0f;
    int cnt4 = (cnt + 3) & ~3;
    for (int e = cnt; e < cnt4; e++) row[e] = 0;   // zero-row padding
    g_cnt[i] = (short)cnt4;
}

// Transpose + hi/lo bf16 split of W [128,128]: wt[idx<8192]=hi pair, wt[8192+idx]=lo pair
// idx = n*64 + p ; holds (W[2p][n], W[2p+1][n]) i.e. W^T row n, k pair 2p.
__global__ void prep_w_kernel(const float* __restrict__ W, unsigned int* __restrict__ wt) {
    int idx = blockIdx.x * blockDim.x + threadIdx.x;
    if (idx >= 8192) return;
    int n = idx >> 6, k = (idx & 63) * 2;
    float x0 = W[k * 128 + n];
    float x1 = W[(k + 1) * 128 + n];
    __nv_bfloat16 h0 = __float2bfloat16(x0);
    __nv_bfloat16 h1 = __float2bfloat16(x1);
    __nv_bfloat16 l0 = __float2bfloat16(x0 - __bfloat162float(h0));
    __nv_bfloat16 l1 = __float2bfloat16(x1 - __bfloat162float(h1));
    wt[idx]        = (unsigned int)__bfloat16_as_ushort(h0) | ((unsigned int)__bfloat16_as_ushort(h1) << 16);
    wt[8192 + idx] = (unsigned int)__bfloat16_as_ushort(l0) | ((unsigned int)__bfloat16_as_ushort(l1) << 16);
}

// ---------------- packed f32x2 helpers ----------------
__device__ __forceinline__ void addx2(unsigned long long& a, unsigned long long b) {
    asm("add.rn.f32x2 %0, %0, %1;" : "+l"(a) : "l"(b));
}
__device__ __forceinline__ unsigned long long mulx2(unsigned long long a, unsigned long long b) {
    unsigned long long r;
    asm("mul.rn.f32x2 %0, %1, %2;" : "=l"(r) : "l"(a), "l"(b));
    return r;
}
__device__ __forceinline__ unsigned long long packx2(float lo, float hi) {
    unsigned long long r;
    asm("mov.b64 %0, {%1, %2};" : "=l"(r) : "f"(lo), "f"(hi));
    return r;
}

// ---------------- polynomial filter (unchanged from R3) ----------------
#define FS 32
#define UROWS (NN_ + 1)
#define POLY_SMEM (NN_*PADN*2 + 2*UROWS*FS*4 + NN_*4 + NN_*2)

__global__ void __launch_bounds__(512, 1) poly_kernel(const float* __restrict__ xin) {
    extern __shared__ unsigned char smraw[];
    unsigned short* nbr_s = (unsigned short*)smraw;
    float* ubuf0          = (float*)(smraw + NN_*PADN*2);
    float* ubuf1          = ubuf0 + UROWS * FS;
    float* dinv_s         = ubuf1 + UROWS * FS;
    short* cnt_s          = (short*)(dinv_s + NN_);

    int g  = blockIdx.y;
    int fb = blockIdx.x * FS;
    int tid = threadIdx.x, w = tid >> 5, l = tid & 31;
    int h  = l >> 4;
    int l2 = l & 15;
    int gbase = (w * 2 + h) * 16;

    {
        const uint4* src = (const uint4*)&g_nbr[(size_t)g * 512 * PADN];
        uint4* dst = (uint4*)nbr_s;
        for (int i = tid; i < 512 * PADN / 8; i += 512) dst[i] = src[i];
    }
    if (tid < 512) {
        dinv_s[tid] = g_dinv[g * 512 + tid];
        cnt_s[tid]  = g_cnt[g * 512 + tid];
    }
    if (tid < 32) ubuf0[tid] = 0.0f;
    else if (tid < 64) ubuf1[tid - 32] = 0.0f;
    __syncthreads();

    unsigned long long acc[16];
    const float* xg = xin + ((size_t)g * 512) * FF + fb + l2 * 2;
#pragma unroll
    for (int m = 0; m < 16; m++) {
        int n = gbase + m;
        float2 xv = *(const float2*)(xg + (size_t)n * FF);
        acc[m] = packx2(xv.x, xv.y);
        unsigned long long dd = packx2(dinv_s[n], dinv_s[n]);
        *(unsigned long long*)(ubuf0 + (n + 1) * FS + l2 * 2) = mulx2(acc[m], dd);
    }
    __syncthreads();

    float* ucur = ubuf0;
    float* unew = ubuf1;
#pragma unroll 1
    for (int hop = 0; hop < 3; hop++) {
        const char* ucb = (const char*)ucur + l2 * 8;
#pragma unroll
        for (int m = 0; m < 16; m++) {
            int n = gbase + m;
            int cnt4 = cnt_s[n];
            const uint2* row = (const uint2*)&nbr_s[n * PADN];
            unsigned long long sa = 0ull, sb = 0ull;
#pragma unroll 1
            for (int e = 0; e < cnt4; e += 4) {
                uint2 p = row[e >> 2];
                unsigned int o0 = p.x & 0xffffu;
                unsigned int o1 = p.x >> 16;
                unsigned int o2 = p.y & 0xffffu;
                unsigned int o3 = p.y >> 16;
                unsigned long long v0 = *(const unsigned long long*)(ucb + (o0 << 3));
                unsigned long long v1 = *(const unsigned long long*)(ucb + (o1 << 3));
                unsigned long long v2 = *(const unsigned long long*)(ucb + (o2 << 3));
                unsigned long long v3 = *(const unsigned long long*)(ucb + (o3 << 3));
                addx2(sa, v0);
                addx2(sb, v1);
                addx2(sa, v2);
                addx2(sb, v3);
            }
            addx2(sa, sb);
            float d = dinv_s[n];
            unsigned long long dd = packx2(d, d);
            unsigned long long zn = mulx2(dd, sa);
            addx2(acc[m], zn);
            *(unsigned long long*)(unew + (n + 1) * FS + l2 * 2) = mulx2(dd, zn);
        }
        __syncthreads();
        float* t = ucur; ucur = unew; unew = t;
    }

    float* yo = g_acc + ((size_t)g * 512) * FF + fb + l2 * 2;
#pragma unroll
    for (int m = 0; m < 16; m++) {
        int n = gbase + m;
        *(unsigned long long*)(yo + (size_t)n * FF) = acc[m];
    }
}

// ---------------- mma.sync GEMM + bias + relu ----------------
// Y[128,128] = relu(A @ W + b) per CTA, bf16 hi/lo split (hi*hi + hi*lo + lo*hi),
// fp32 accum. 256 threads = 8 warps; warp (wr,wc) owns rows 32*wr..+31, cols 64*wc..+63.
// Smem: Ah/Al/Bh/Bl as bf16 [128][136] (stride 136 -> conflict-free frag loads).

#define ASTR 136
#define GMM_AH 0
#define GMM_AL (GMM_AH + 128*ASTR*2)
#define GMM_BH (GMM_AL + 128*ASTR*2)
#define GMM_BL (GMM_BH + 128*ASTR*2)
#define GMM_BIAS (GMM_BL + 128*ASTR*2)
#define GEMM_MMA_SMEM (GMM_BIAS + 128*4)

__device__ __forceinline__ void mma16816(float* c, const unsigned* a, const unsigned* b) {
    asm volatile(
        "mma.sync.aligned.m16n8k16.row.col.f32.bf16.bf16.f32 "
        "{%0,%1,%2,%3}, {%4,%5,%6,%7}, {%8,%9}, {%0,%1,%2,%3};"
        : "+f"(c[0]), "+f"(c[1]), "+f"(c[2]), "+f"(c[3])
        : "r"(a[0]), "r"(a[1]), "r"(a[2]), "r"(a[3]), "r"(b[0]), "r"(b[1]));
}

__global__ void __launch_bounds__(256, 1) gemm_mma_kernel(
        const float* __restrict__ A, const unsigned int* __restrict__ wt,
        const float* __restrict__ bias, float* __restrict__ Y) {
    extern __shared__ unsigned char smg[];
    unsigned short* Ah = (unsigned short*)(smg + GMM_AH);
    unsigned short* Al = (unsigned short*)(smg + GMM_AL);
    unsigned short* Bh = (unsigned short*)(smg + GMM_BH);
    unsigned short* Bl = (unsigned short*)(smg + GMM_BL);
    float* bias_s = (float*)(smg + GMM_BIAS);

    int tid = threadIdx.x;
    int lane = tid & 31;
    int w = tid >> 5;
    int wr = w & 3;            // row group: rows 32*wr..32*wr+31
    int wc = w >> 2;           // col group: cols 64*wc..64*wc+63
    size_t rowbase = (size_t)blockIdx.x * 128;

    // B tiles: pre-split W^T pairs -> padded smem
    for (int idx = tid; idx < 8192; idx += 256) {
        int n = idx >> 6, p = idx & 63;
        *(unsigned int*)&Bh[n * ASTR + 2 * p] = wt[idx];
        *(unsigned int*)&Bl[n * ASTR + 2 * p] = wt[8192 + idx];
    }
    // A tiles: load fp32, split hi/lo
    for (int idx = tid; idx < 8192; idx += 256) {
        int r = idx >> 6, p = idx & 63;
        float2 x = *(const float2*)(A + (rowbase + r) * 128 + 2 * p);
        __nv_bfloat16 h0 = __float2bfloat16(x.x);
        __nv_bfloat16 h1 = __float2bfloat16(x.y);
        __nv_bfloat16 l0 = __float2bfloat16(x.x - __bfloat162float(h0));
        __nv_bfloat16 l1 = __float2bfloat16(x.y - __bfloat162float(h1));
        *(unsigned int*)&Ah[r * ASTR + 2 * p] =
            (unsigned int)__bfloat16_as_ushort(h0) | ((unsigned int)__bfloat16_as_ushort(h1) << 16);
        *(unsigned int*)&Al[r * ASTR + 2 * p] =
            (unsigned int)__bfloat16_as_ushort(l0) | ((unsigned int)__bfloat16_as_ushort(l1) << 16);
    }
    if (tid < 128) bias_s[tid] = bias[tid];
    __syncthreads();

    float acc[2][8][4];
#pragma unroll
    for (int mt = 0; mt < 2; mt++)
#pragma unroll
        for (int nt = 0; nt < 8; nt++)
#pragma unroll
            for (int q = 0; q < 4; q++) acc[mt][nt][q] = 0.0f;

    int frow = lane >> 2;          // fragment row within tile
    int fcolb = 2 * (lane & 3);    // fragment k-pair base

#pragma unroll
    for (int kk = 0; kk < 8; kk++) {
        int kc = fcolb + 16 * kk;
        unsigned ah[2][4], al[2][4], bh[8][2], bl[8][2];
#pragma unroll
        for (int mt = 0; mt < 2; mt++) {
            int r0 = 32 * wr + 16 * mt + frow;
            ah[mt][0] = *(const unsigned*)&Ah[r0 * ASTR + kc];
            ah[mt][1] = *(const unsigned*)&Ah[(r0 + 8) * ASTR + kc];
            ah[mt][2] = *(const unsigned*)&Ah[r0 * ASTR + kc + 8];
            ah[mt][3] = *(const unsigned*)&Ah[(r0 + 8) * ASTR + kc + 8];
            al[mt][0] = *(const unsigned*)&Al[r0 * ASTR + kc];
            al[mt][1] = *(const unsigned*)&Al[(r0 + 8) * ASTR + kc];
            al[mt][2] = *(const unsigned*)&Al[r0 * ASTR + kc + 8];
            al[mt][3] = *(const unsigned*)&Al[(r0 + 8) * ASTR + kc + 8];
        }
#pragma unroll
        for (int nt = 0; nt < 8; nt++) {
            int n0 = 64 * wc + 8 * nt + frow;
            bh[nt][0] = *(const unsigned*)&Bh[n0 * ASTR + kc];
            bh[nt][1] = *(const unsigned*)&Bh[n0 * ASTR + kc + 8];
            bl[nt][0] = *(const unsigned*)&Bl[n0 * ASTR + kc];
            bl[nt][1] = *(const unsigned*)&Bl[n0 * ASTR + kc + 8];
        }
#pragma unroll
        for (int mt = 0; mt < 2; mt++)
#pragma unroll
            for (int nt = 0; nt < 8; nt++) {
                mma16816(acc[mt][nt], ah[mt], bh[nt]);   // hi*hi
                mma16816(acc[mt][nt], ah[mt], bl[nt]);   // hi*lo
                mma16816(acc[mt][nt], al[mt], bh[nt]);   // lo*hi
            }
    }

    // epilogue: bias + relu + store
#pragma unroll
    for (int mt = 0; mt < 2; mt++) {
        size_t r0 = rowbase + 32 * wr + 16 * mt + frow;
#pragma unroll
        for (int nt = 0; nt < 8; nt++) {
            int col = 64 * wc + 8 * nt + fcolb;
            float b0 = bias_s[col], b1 = bias_s[col + 1];
            float2 v0, v1;
            float t;
            t = acc[mt][nt][0] + b0; v0.x = t > 0 ? t : 0;
            t = acc[mt][nt][1] + b1; v0.y = t > 0 ? t : 0;
            t = acc[mt][nt][2] + b0; v1.x = t > 0 ? t : 0;
            t = acc[mt][nt][3] + b1; v1.y = t > 0 ? t : 0;
            *(float2*)(Y + r0 * 128 + col)       = v0;
            *(float2*)(Y + (r0 + 8) * 128 + col) = v1;
        }
    }
}

// ---------------- head: mean pool -> relu(h@Wr1+br1) -> h@Wr2+br2 ----------------
__global__ void __launch_bounds__(512) head_kernel(
        const float* __restrict__ Wr1, const float* __restrict__ br1,
        const float* __restrict__ Wr2, const float* __restrict__ br2,
        float* __restrict__ out) {
    __shared__ float part[4][128];
    __shared__ float hs[128];
    __shared__ float rs[64];
    int g = blockIdx.x;
    int tid = threadIdx.x;
    int f = tid & 127, q = tid >> 7;

    const float* yg = g_y + (size_t)g * 512 * 128;
    float s = 0.0f;
    for (int n = q * 128; n < q * 128 + 128; n++) s += yg[(size_t)n * 128 + f];
    part[q][f] = s;
    __syncthreads();

    if (tid < 128)
        hs[tid] = (part[0][tid] + part[1][tid] + part[2][tid] + part[3][tid]) * (1.0f / 512.0f);
    __syncthreads();

    if (tid < 64) {
        float a = br1[tid];
        for (int k = 0; k < 128; k++) a += hs[k] * Wr1[k * 64 + tid];
        rs[tid] = a > 0 ? a : 0;
    }
    __syncthreads();

    if (tid == 0) {
        float a = br2[0];
        for (int o = 0; o < 64; o++) a += rs[o] * Wr2[o];
        out[g] = a;
    }
}

// ---------------- launch ----------------
extern "C" void kernel_launch(void* const* d_in, const int* in_sizes, int n_in,
                              void* d_out, int out_size) {
    const float* X   = (const float*)d_in[0];
    const int*   ei  = (const int*)d_in[2];
    const float* W1  = (const float*)d_in[3];
    const float* b1  = (const float*)d_in[4];
    const float* W2  = (const float*)d_in[5];
    const float* b2  = (const float*)d_in[6];
    const float* Wr1 = (const float*)d_in[7];
    const float* br1 = (const float*)d_in[8];
    const float* Wr2 = (const float*)d_in[9];
    const float* br2 = (const float*)d_in[10];
    float* out = (float*)d_out;

    cudaFuncSetAttribute(poly_kernel, cudaFuncAttributeMaxDynamicSharedMemorySize, POLY_SMEM);
    cudaFuncSetAttribute(gemm_mma_kernel, cudaFuncAttributeMaxDynamicSharedMemorySize, GEMM_MMA_SMEM);

    void* yaddr = nullptr;
    cudaGetSymbolAddress(&yaddr, g_y);
    float* Yp = (float*)yaddr;
    void* aaddr = nullptr;
    cudaGetSymbolAddress(&aaddr, g_acc);
    const float* Ap = (const float*)aaddr;
    void* w1addr = nullptr; cudaGetSymbolAddress(&w1addr, g_wt1);
    void* w2addr = nullptr; cudaGetSymbolAddress(&w2addr, g_wt2);

    // adjacency (rebuilt every call; deterministic)
    clear_adj_kernel<<<ADJ_WORDS / 256, 256>>>();
    build_adj_kernel<<<ETOT / 256, 256>>>(ei);
    expand_kernel<<<NTOT / 256, 256>>>();
    prep_w_kernel<<<32, 256>>>(W1, (unsigned int*)w1addr);
    prep_w_kernel<<<32, 256>>>(W2, (unsigned int*)w2addr);

    dim3 pgrid(FF / FS, BG);

    // layer 1
    poly_kernel<<<pgrid, 512, POLY_SMEM>>>(X);
    gemm_mma_kernel<<<NTOT / 128, 256, GEMM_MMA_SMEM>>>(Ap, (const unsigned int*)w1addr, b1, Yp);
    // layer 2
    poly_kernel<<<pgrid, 512, POLY_SMEM>>>(Yp);
    gemm_mma_kernel<<<NTOT / 128, 256, GEMM_MMA_SMEM>>>(Ap, (const unsigned int*)w2addr, b2, Yp);
    // head
    head_kernel<<<BG, 512>>>(Wr1, br1, Wr2, br2, out);
}

// round 6
// speedup vs baseline: 3.1965x; 1.0304x over previous
#include <cuda_runtime.h>
#include <cuda_bf16.h>

// Problem constants (fixed by the reference)
#define BG   128              // graphs
#define NN_  512              // nodes per graph
#define FF   128              // feature dim
#define DEG  16
#define ETOT (BG*NN_*DEG)     // 1,048,576 edges
#define NTOT (BG*NN_)         // 65,536 nodes
#define ADJ_WORDS (BG*NN_*(NN_/32))  // 4MB bitmask
#define PADN 64               // padded neighbor-list stride (multiple of 4)

// -------- device-global scratch (no allocations allowed) --------
__device__ unsigned int   g_adj[ADJ_WORDS];
__device__ unsigned short g_nbr[(size_t)NTOT * PADN];  // offsets = node*8 (16B units)
__device__ short          g_cnt[NTOT];                  // cnt4 (padded to mult of 4)
__device__ float          g_dinv[NTOT];
__device__ unsigned int   g_pc[NTOT];                   // degree-sorted: node | cnt4<<16
__device__ float g_acc[(size_t)NTOT * FF];   // 32MB
__device__ float g_y[(size_t)NTOT * FF];     // 32MB
__device__ unsigned int g_wt1[16384];        // W1^T split: hi pairs / lo pairs
__device__ unsigned int g_wt2[16384];        // W2^T split

// ---------------- adjacency build ----------------
__global__ void clear_adj_kernel() {
    int i = blockIdx.x * blockDim.x + threadIdx.x;
    if (i < ADJ_WORDS) g_adj[i] = 0u;
}

__global__ void build_adj_kernel(const int* __restrict__ ei) {
    int e = blockIdx.x * blockDim.x + threadIdx.x;
    if (e >= ETOT) return;
    int src = ei[e];
    int dst = ei[ETOT + e];
    int g  = src >> 9;         // N = 512
    int si = src & 511;
    int di = dst & 511;
    atomicOr(&g_adj[(g * 512 + si) * 16 + (di >> 5)], 1u << (di & 31));
}

// Expand bitmask rows into padded u16 offset lists (node*8, 16B units).
// Zero row lives at node index 512 -> offset 4096. Pad cnt to multiple of 4.
__global__ void expand_kernel() {
    int i = blockIdx.x * blockDim.x + threadIdx.x;   // node id
    if (i >= NTOT) return;
    int cnt = 0;
    unsigned short* row = &g_nbr[(size_t)i * PADN];
#pragma unroll
    for (int w = 0; w < 16; w++) {
        unsigned int bits = g_adj[i * 16 + w];
        while (bits) {
            int b = __ffs(bits) - 1;
            bits &= bits - 1;
            if (cnt < PADN) row[cnt] = (unsigned short)((w * 32 + b) * 8);
            cnt++;
        }
    }
    if (cnt > PADN) cnt = PADN;
    g_dinv[i] = (cnt > 0) ? rsqrtf((float)cnt) : 0.0f;
    int cnt4 = (cnt + 3) & ~3;
    for (int e = cnt; e < cnt4; e++) row[e] = (unsigned short)4096;  // zero row
    g_cnt[i] = (short)cnt4;
}

// Counting sort by degree per graph -> g_pc[g*512 + pos] = node | cnt4<<16
__global__ void __launch_bounds__(512) sort_kernel() {
    __shared__ unsigned hist[17];
    __shared__ unsigned base[17];
    int g = blockIdx.x, tid = threadIdx.x;
    if (tid < 17) hist[tid] = 0;
    __syncthreads();
    int cnt4 = g_cnt[g * 512 + tid];
    int bin = cnt4 >> 2;   // 0..16
    atomicAdd(&hist[bin], 1);
    __syncthreads();
    if (tid == 0) {
        unsigned s = 0;
        for (int i = 0; i < 17; i++) { base[i] = s; s += hist[i]; }
    }
    __syncthreads();
    unsigned pos = atomicAdd(&base[bin], 1);
    g_pc[g * 512 + pos] = (unsigned)tid | ((unsigned)cnt4 << 16);
}

// Transpose + hi/lo bf16 split of both weights in one launch.
__global__ void prep_w_kernel(const float* __restrict__ W1, const float* __restrict__ W2,
                              unsigned int* __restrict__ wt1, unsigned int* __restrict__ wt2) {
    int idx = blockIdx.x * blockDim.x + threadIdx.x;
    const float* W = (idx < 8192) ? W1 : W2;
    unsigned int* wt = (idx < 8192) ? wt1 : wt2;
    int id = idx & 8191;
    int n = id >> 6, k = (id & 63) * 2;
    float x0 = W[k * 128 + n];
    float x1 = W[(k + 1) * 128 + n];
    __nv_bfloat16 h0 = __float2bfloat16(x0);
    __nv_bfloat16 h1 = __float2bfloat16(x1);
    __nv_bfloat16 l0 = __float2bfloat16(x0 - __bfloat162float(h0));
    __nv_bfloat16 l1 = __float2bfloat16(x1 - __bfloat162float(h1));
    wt[id]        = (unsigned int)__bfloat16_as_ushort(h0) | ((unsigned int)__bfloat16_as_ushort(h1) << 16);
    wt[8192 + id] = (unsigned int)__bfloat16_as_ushort(l0) | ((unsigned int)__bfloat16_as_ushort(l1) << 16);
}

// ---------------- packed f32x2 helpers ----------------
__device__ __forceinline__ void addx2(unsigned long long& a, unsigned long long b) {
    asm("add.rn.f32x2 %0, %0, %1;" : "+l"(a) : "l"(b));
}
__device__ __forceinline__ unsigned long long mulx2(unsigned long long a, unsigned long long b) {
    unsigned long long r;
    asm("mul.rn.f32x2 %0, %1, %2;" : "=l"(r) : "l"(a), "l"(b));
    return r;
}
__device__ __forceinline__ unsigned long long packx2(float lo, float hi) {
    unsigned long long r;
    asm("mov.b64 %0, {%1, %2};" : "=l"(r) : "f"(lo), "f"(hi));
    return r;
}

// ---------------- polynomial filter: acc = sum_{k=0..3} S^k x ----------------
// One CTA per (graph, 32-col slice). Quarter-warp (8 lanes x float4) per row,
// rows assigned in degree-sorted order (4 similar-degree rows per warp).
// u-space recurrence: u0 = dinv*x ; hop: s = gather(u), z = dinv*s (acc+=z), u' = dinv*z.
#define FS 32
#define UROWS 513                        // row 512 = zero row
#define POLY_NBR  0
#define POLY_U0   (NN_*PADN*2)                    // 65536
#define POLY_U1   (POLY_U0 + UROWS*FS*4)          // +65664
#define POLY_DINV (POLY_U1 + UROWS*FS*4)          // +65664
#define POLY_PC   (POLY_DINV + NN_*4)
#define POLY_SMEM (POLY_PC + NN_*4)

__global__ void __launch_bounds__(512, 1) poly_kernel(const float* __restrict__ xin) {
    extern __shared__ unsigned char smraw[];
    unsigned short* nbr_s = (unsigned short*)(smraw + POLY_NBR);
    float* ubuf0          = (float*)(smraw + POLY_U0);
    float* ubuf1          = (float*)(smraw + POLY_U1);
    float* dinv_s         = (float*)(smraw + POLY_DINV);
    unsigned* pc_s        = (unsigned*)(smraw + POLY_PC);

    int g  = blockIdx.y;
    int fb = blockIdx.x * FS;
    int tid = threadIdx.x, w = tid >> 5, lane = tid & 31;
    int q  = lane >> 3;            // quarter-warp id 0..3
    int li = lane & 7;             // lane in quarter-warp; cols li*4..li*4+3
    int pbase = w * 4 + q;         // sorted position base; row at m*64 + pbase

    // load neighbor offset lists (uint4 = 8 u16 per load)
    {
        const uint4* src = (const uint4*)&g_nbr[(size_t)g * 512 * PADN];
        uint4* dst = (uint4*)nbr_s;
        for (int i = tid; i < 512 * PADN / 8; i += 512) dst[i] = src[i];
    }
    if (tid < 512) {
        dinv_s[tid] = g_dinv[g * 512 + tid];
        pc_s[tid]   = g_pc[g * 512 + tid];
    }
    // zero row 512 of both u buffers
    if (tid < 32) ubuf0[512 * FS + tid] = 0.0f;
    else if (tid < 64) ubuf1[512 * FS + (tid - 32)] = 0.0f;
    __syncthreads();

    // per-m row metadata in registers (fixed across hops)
    int roff[8];                       // row*128 : byte offset into nbr rows AND u rows
    int cntm[8];
    unsigned long long ddm[8];
    unsigned long long accA[8], accB[8];

    const char* xbase = (const char*)(xin + (size_t)g * 512 * FF + fb) + li * 16;
#pragma unroll
    for (int m = 0; m < 8; m++) {
        unsigned pc = pc_s[m * 64 + pbase];
        int row = pc & 0xffffu;
        cntm[m] = pc >> 16;
        roff[m] = row * 128;
        float d = dinv_s[row];
        ddm[m] = packx2(d, d);
        ulonglong2 xv = *(const ulonglong2*)(xbase + (size_t)row * 512);
        accA[m] = xv.x; accB[m] = xv.y;
        ulonglong2 uw;
        uw.x = mulx2(ddm[m], accA[m]);
        uw.y = mulx2(ddm[m], accB[m]);
        *(ulonglong2*)((char*)ubuf0 + roff[m] + li * 16) = uw;
    }
    __syncthreads();

    float* ucur = ubuf0;
    float* unew = ubuf1;
#pragma unroll 1
    for (int hop = 0; hop < 3; hop++) {
        const char* ucb = (const char*)ucur + li * 16;   // gather base (+node*128)
#pragma unroll
        for (int m = 0; m < 8; m++) {
            const uint2* rowp = (const uint2*)((const char*)nbr_s + roff[m]);
            int cnt4 = cntm[m];
            unsigned long long sa0 = 0ull, sa1 = 0ull, sb0 = 0ull, sb1 = 0ull;
#pragma unroll 1
            for (int e = 0; e < cnt4; e += 4) {
                uint2 pk = rowp[e >> 2];
                unsigned o0 = pk.x & 0xffffu, o1 = pk.x >> 16;
                unsigned o2 = pk.y & 0xffffu, o3 = pk.y >> 16;
                ulonglong2 v0 = *(const ulonglong2*)(ucb + ((size_t)o0 << 4));
                ulonglong2 v1 = *(const ulonglong2*)(ucb + ((size_t)o1 << 4));
                ulonglong2 v2 = *(const ulonglong2*)(ucb + ((size_t)o2 << 4));
                ulonglong2 v3 = *(const ulonglong2*)(ucb + ((size_t)o3 << 4));
                addx2(sa0, v0.x); addx2(sa1, v0.y);
                addx2(sb0, v1.x); addx2(sb1, v1.y);
                addx2(sa0, v2.x); addx2(sa1, v2.y);
                addx2(sb0, v3.x); addx2(sb1, v3.y);
            }
            addx2(sa0, sb0); addx2(sa1, sb1);
            unsigned long long zn0 = mulx2(ddm[m], sa0);
            unsigned long long zn1 = mulx2(ddm[m], sa1);
            addx2(accA[m], zn0); addx2(accB[m], zn1);
            ulonglong2 uw;
            uw.x = mulx2(ddm[m], zn0);
            uw.y = mulx2(ddm[m], zn1);
            *(ulonglong2*)((char*)unew + roff[m] + li * 16) = uw;
        }
        __syncthreads();
        float* t = ucur; ucur = unew; unew = t;
    }

    char* ybase = (char*)(g_acc + (size_t)g * 512 * FF + fb) + li * 16;
#pragma unroll
    for (int m = 0; m < 8; m++) {
        ulonglong2 ov; ov.x = accA[m]; ov.y = accB[m];
        *(ulonglong2*)(ybase + (size_t)roff[m] * 4) = ov;
    }
}

// ---------------- mma.sync GEMM + bias + relu (unchanged from R5) ----------------
#define ASTR 136
#define GMM_AH 0
#define GMM_AL (GMM_AH + 128*ASTR*2)
#define GMM_BH (GMM_AL + 128*ASTR*2)
#define GMM_BL (GMM_BH + 128*ASTR*2)
#define GMM_BIAS (GMM_BL + 128*ASTR*2)
#define GEMM_MMA_SMEM (GMM_BIAS + 128*4)

__device__ __forceinline__ void mma16816(float* c, const unsigned* a, const unsigned* b) {
    asm volatile(
        "mma.sync.aligned.m16n8k16.row.col.f32.bf16.bf16.f32 "
        "{%0,%1,%2,%3}, {%4,%5,%6,%7}, {%8,%9}, {%0,%1,%2,%3};"
        : "+f"(c[0]), "+f"(c[1]), "+f"(c[2]), "+f"(c[3])
        : "r"(a[0]), "r"(a[1]), "r"(a[2]), "r"(a[3]), "r"(b[0]), "r"(b[1]));
}

__global__ void __launch_bounds__(256, 1) gemm_mma_kernel(
        const float* __restrict__ A, const unsigned int* __restrict__ wt,
        const float* __restrict__ bias, float* __restrict__ Y) {
    extern __shared__ unsigned char smg[];
    unsigned short* Ah = (unsigned short*)(smg + GMM_AH);
    unsigned short* Al = (unsigned short*)(smg + GMM_AL);
    unsigned short* Bh = (unsigned short*)(smg + GMM_BH);
    unsigned short* Bl = (unsigned short*)(smg + GMM_BL);
    float* bias_s = (float*)(smg + GMM_BIAS);

    int tid = threadIdx.x;
    int lane = tid & 31;
    int w = tid >> 5;
    int wr = w & 3;
    int wc = w >> 2;
    size_t rowbase = (size_t)blockIdx.x * 128;

    for (int idx = tid; idx < 8192; idx += 256) {
        int n = idx >> 6, p = idx & 63;
        *(unsigned int*)&Bh[n * ASTR + 2 * p] = wt[idx];
        *(unsigned int*)&Bl[n * ASTR + 2 * p] = wt[8192 + idx];
    }
    for (int idx = tid; idx < 8192; idx += 256) {
        int r = idx >> 6, p = idx & 63;
        float2 x = *(const float2*)(A + (rowbase + r) * 128 + 2 * p);
        __nv_bfloat16 h0 = __float2bfloat16(x.x);
        __nv_bfloat16 h1 = __float2bfloat16(x.y);
        __nv_bfloat16 l0 = __float2bfloat16(x.x - __bfloat162float(h0));
        __nv_bfloat16 l1 = __float2bfloat16(x.y - __bfloat162float(h1));
        *(unsigned int*)&Ah[r * ASTR + 2 * p] =
            (unsigned int)__bfloat16_as_ushort(h0) | ((unsigned int)__bfloat16_as_ushort(h1) << 16);
        *(unsigned int*)&Al[r * ASTR + 2 * p] =
            (unsigned int)__bfloat16_as_ushort(l0) | ((unsigned int)__bfloat16_as_ushort(l1) << 16);
    }
    if (tid < 128) bias_s[tid] = bias[tid];
    __syncthreads();

    float acc[2][8][4];
#pragma unroll
    for (int mt = 0; mt < 2; mt++)
#pragma unroll
        for (int nt = 0; nt < 8; nt++)
#pragma unroll
            for (int p = 0; p < 4; p++) acc[mt][nt][p] = 0.0f;

    int frow = lane >> 2;
    int fcolb = 2 * (lane & 3);

#pragma unroll
    for (int kk = 0; kk < 8; kk++) {
        int kc = fcolb + 16 * kk;
        unsigned ah[2][4], al[2][4], bh[8][2], bl[8][2];
#pragma unroll
        for (int mt = 0; mt < 2; mt++) {
            int r0 = 32 * wr + 16 * mt + frow;
            ah[mt][0] = *(const unsigned*)&Ah[r0 * ASTR + kc];
            ah[mt][1] = *(const unsigned*)&Ah[(r0 + 8) * ASTR + kc];
            ah[mt][2] = *(const unsigned*)&Ah[r0 * ASTR + kc + 8];
            ah[mt][3] = *(const unsigned*)&Ah[(r0 + 8) * ASTR + kc + 8];
            al[mt][0] = *(const unsigned*)&Al[r0 * ASTR + kc];
            al[mt][1] = *(const unsigned*)&Al[(r0 + 8) * ASTR + kc];
            al[mt][2] = *(const unsigned*)&Al[r0 * ASTR + kc + 8];
            al[mt][3] = *(const unsigned*)&Al[(r0 + 8) * ASTR + kc + 8];
        }
#pragma unroll
        for (int nt = 0; nt < 8; nt++) {
            int n0 = 64 * wc + 8 * nt + frow;
            bh[nt][0] = *(const unsigned*)&Bh[n0 * ASTR + kc];
            bh[nt][1] = *(const unsigned*)&Bh[n0 * ASTR + kc + 8];
            bl[nt][0] = *(const unsigned*)&Bl[n0 * ASTR + kc];
            bl[nt][1] = *(const unsigned*)&Bl[n0 * ASTR + kc + 8];
        }
#pragma unroll
        for (int mt = 0; mt < 2; mt++)
#pragma unroll
            for (int nt = 0; nt < 8; nt++) {
                mma16816(acc[mt][nt], ah[mt], bh[nt]);
                mma16816(acc[mt][nt], ah[mt], bl[nt]);
                mma16816(acc[mt][nt], al[mt], bh[nt]);
            }
    }

#pragma unroll
    for (int mt = 0; mt < 2; mt++) {
        size_t r0 = rowbase + 32 * wr + 16 * mt + frow;
#pragma unroll
        for (int nt = 0; nt < 8; nt++) {
            int col = 64 * wc + 8 * nt + fcolb;
            float b0 = bias_s[col], b1 = bias_s[col + 1];
            float2 v0, v1;
            float t;
            t = acc[mt][nt][0] + b0; v0.x = t > 0 ? t : 0;
            t = acc[mt][nt][1] + b1; v0.y = t > 0 ? t : 0;
            t = acc[mt][nt][2] + b0; v1.x = t > 0 ? t : 0;
            t = acc[mt][nt][3] + b1; v1.y = t > 0 ? t : 0;
            *(float2*)(Y + r0 * 128 + col)       = v0;
            *(float2*)(Y + (r0 + 8) * 128 + col) = v1;
        }
    }
}

// ---------------- head ----------------
__global__ void __launch_bounds__(512) head_kernel(
        const float* __restrict__ Wr1, const float* __restrict__ br1,
        const float* __restrict__ Wr2, const float* __restrict__ br2,
        float* __restrict__ out) {
    __shared__ float part[4][128];
    __shared__ float hs[128];
    __shared__ float rs[64];
    int g = blockIdx.x;
    int tid = threadIdx.x;
    int f = tid & 127, q = tid >> 7;

    const float* yg = g_y + (size_t)g * 512 * 128;
    float s = 0.0f;
    for (int n = q * 128; n < q * 128 + 128; n++) s += yg[(size_t)n * 128 + f];
    part[q][f] = s;
    __syncthreads();

    if (tid < 128)
        hs[tid] = (part[0][tid] + part[1][tid] + part[2][tid] + part[3][tid]) * (1.0f / 512.0f);
    __syncthreads();

    if (tid < 64) {
        float a = br1[tid];
        for (int k = 0; k < 128; k++) a += hs[k] * Wr1[k * 64 + tid];
        rs[tid] = a > 0 ? a : 0;
    }
    __syncthreads();

    if (tid == 0) {
        float a = br2[0];
        for (int o = 0; o < 64; o++) a += rs[o] * Wr2[o];
        out[g] = a;
    }
}

// ---------------- launch ----------------
extern "C" void kernel_launch(void* const* d_in, const int* in_sizes, int n_in,
                              void* d_out, int out_size) {
    const float* X   = (const float*)d_in[0];
    const int*   ei  = (const int*)d_in[2];
    const float* W1  = (const float*)d_in[3];
    const float* b1  = (const float*)d_in[4];
    const float* W2  = (const float*)d_in[5];
    const float* b2  = (const float*)d_in[6];
    const float* Wr1 = (const float*)d_in[7];
    const float* br1 = (const float*)d_in[8];
    const float* Wr2 = (const float*)d_in[9];
    const float* br2 = (const float*)d_in[10];
    float* out = (float*)d_out;

    cudaFuncSetAttribute(poly_kernel, cudaFuncAttributeMaxDynamicSharedMemorySize, POLY_SMEM);
    cudaFuncSetAttribute(gemm_mma_kernel, cudaFuncAttributeMaxDynamicSharedMemorySize, GEMM_MMA_SMEM);

    void* yaddr = nullptr;  cudaGetSymbolAddress(&yaddr, g_y);
    float* Yp = (float*)yaddr;
    void* aaddr = nullptr;  cudaGetSymbolAddress(&aaddr, g_acc);
    const float* Ap = (const float*)aaddr;
    void* w1addr = nullptr; cudaGetSymbolAddress(&w1addr, g_wt1);
    void* w2addr = nullptr; cudaGetSymbolAddress(&w2addr, g_wt2);

    // adjacency (rebuilt every call; deterministic)
    clear_adj_kernel<<<ADJ_WORDS / 256, 256>>>();
    build_adj_kernel<<<ETOT / 256, 256>>>(ei);
    expand_kernel<<<NTOT / 256, 256>>>();
    sort_kernel<<<BG, 512>>>();
    prep_w_kernel<<<64, 256>>>(W1, W2, (unsigned int*)w1addr, (unsigned int*)w2addr);

    dim3 pgrid(FF / FS, BG);

    // layer 1
    poly_kernel<<<pgrid, 512, POLY_SMEM>>>(X);
    gemm_mma_kernel<<<NTOT / 128, 256, GEMM_MMA_SMEM>>>(Ap, (const unsigned int*)w1addr, b1, Yp);
    // layer 2
    poly_kernel<<<pgrid, 512, POLY_SMEM>>>(Yp);
    gemm_mma_kernel<<<NTOT / 128, 256, GEMM_MMA_SMEM>>>(Ap, (const unsigned int*)w2addr, b2, Yp);
    // head
    head_kernel<<<BG, 512>>>(Wr1, br1, Wr2, br2, out);
}

// round 7
// speedup vs baseline: 3.5444x; 1.1088x over previous
#include <cuda_runtime.h>
#include <cuda_bf16.h>

// Problem constants (fixed by the reference)
#define BG   128              // graphs
#define NN_  512              // nodes per graph
#define FF   128              // feature dim
#define DEG  16
#define ETOT (BG*NN_*DEG)     // 1,048,576 edges
#define NTOT (BG*NN_)         // 65,536 nodes
#define ADJ_WORDS (BG*NN_*(NN_/32))  // 4MB bitmask
#define PADN 64               // padded neighbor-list stride (multiple of 4)

// -------- device-global scratch (no allocations allowed) --------
__device__ unsigned int   g_adj[ADJ_WORDS];
__device__ unsigned short g_nbr[(size_t)NTOT * PADN];  // offsets = node*8 (16B units)
__device__ short          g_cnt[NTOT];                  // cnt4 (padded to mult of 4)
__device__ float          g_dinv[NTOT];
__device__ unsigned int   g_pc[NTOT];                   // degree-sorted: node | cnt4<<16
__device__ float g_acc[(size_t)NTOT * FF];   // 32MB
__device__ float g_y[(size_t)NTOT * FF];     // 32MB
__device__ unsigned int g_wt1[16384];        // W1^T split: hi pairs / lo pairs
__device__ unsigned int g_wt2[16384];        // W2^T split

// ---------------- adjacency build ----------------
__global__ void clear_adj_kernel() {
    int i = blockIdx.x * blockDim.x + threadIdx.x;
    if (i < ADJ_WORDS) g_adj[i] = 0u;
}

__global__ void build_adj_kernel(const int* __restrict__ ei) {
    int e = blockIdx.x * blockDim.x + threadIdx.x;
    if (e >= ETOT) return;
    int src = ei[e];
    int dst = ei[ETOT + e];
    int g  = src >> 9;         // N = 512
    int si = src & 511;
    int di = dst & 511;
    atomicOr(&g_adj[(g * 512 + si) * 16 + (di >> 5)], 1u << (di & 31));
}

// Expand bitmask rows into padded u16 offset lists (node*8, 16B units).
// Zero row lives at node index 512 -> offset 4096. Pad cnt to multiple of 4.
__global__ void expand_kernel() {
    int i = blockIdx.x * blockDim.x + threadIdx.x;   // node id
    if (i >= NTOT) return;
    int cnt = 0;
    unsigned short* row = &g_nbr[(size_t)i * PADN];
#pragma unroll
    for (int w = 0; w < 16; w++) {
        unsigned int bits = g_adj[i * 16 + w];
        while (bits) {
            int b = __ffs(bits) - 1;
            bits &= bits - 1;
            if (cnt < PADN) row[cnt] = (unsigned short)((w * 32 + b) * 8);
            cnt++;
        }
    }
    if (cnt > PADN) cnt = PADN;
    g_dinv[i] = (cnt > 0) ? rsqrtf((float)cnt) : 0.0f;
    int cnt4 = (cnt + 3) & ~3;
    for (int e = cnt; e < cnt4; e++) row[e] = (unsigned short)4096;  // zero row
    g_cnt[i] = (short)cnt4;
}

// Counting sort by degree per graph -> g_pc[g*512 + pos] = node | cnt4<<16
__global__ void __launch_bounds__(512) sort_kernel() {
    __shared__ unsigned hist[17];
    __shared__ unsigned base[17];
    int g = blockIdx.x, tid = threadIdx.x;
    if (tid < 17) hist[tid] = 0;
    __syncthreads();
    int cnt4 = g_cnt[g * 512 + tid];
    int bin = cnt4 >> 2;   // 0..16
    atomicAdd(&hist[bin], 1);
    __syncthreads();
    if (tid == 0) {
        unsigned s = 0;
        for (int i = 0; i < 17; i++) { base[i] = s; s += hist[i]; }
    }
    __syncthreads();
    unsigned pos = atomicAdd(&base[bin], 1);
    g_pc[g * 512 + pos] = (unsigned)tid | ((unsigned)cnt4 << 16);
}

// Transpose + hi/lo bf16 split of both weights in one launch.
__global__ void prep_w_kernel(const float* __restrict__ W1, const float* __restrict__ W2,
                              unsigned int* __restrict__ wt1, unsigned int* __restrict__ wt2) {
    int idx = blockIdx.x * blockDim.x + threadIdx.x;
    const float* W = (idx < 8192) ? W1 : W2;
    unsigned int* wt = (idx < 8192) ? wt1 : wt2;
    int id = idx & 8191;
    int n = id >> 6, k = (id & 63) * 2;
    float x0 = W[k * 128 + n];
    float x1 = W[(k + 1) * 128 + n];
    __nv_bfloat16 h0 = __float2bfloat16(x0);
    __nv_bfloat16 h1 = __float2bfloat16(x1);
    __nv_bfloat16 l0 = __float2bfloat16(x0 - __bfloat162float(h0));
    __nv_bfloat16 l1 = __float2bfloat16(x1 - __bfloat162float(h1));
    wt[id]        = (unsigned int)__bfloat16_as_ushort(h0) | ((unsigned int)__bfloat16_as_ushort(h1) << 16);
    wt[8192 + id] = (unsigned int)__bfloat16_as_ushort(l0) | ((unsigned int)__bfloat16_as_ushort(l1) << 16);
}

// ---------------- packed f32x2 helpers ----------------
__device__ __forceinline__ void addx2(unsigned long long& a, unsigned long long b) {
    asm("add.rn.f32x2 %0, %0, %1;" : "+l"(a) : "l"(b));
}
__device__ __forceinline__ unsigned long long mulx2(unsigned long long a, unsigned long long b) {
    unsigned long long r;
    asm("mul.rn.f32x2 %0, %1, %2;" : "=l"(r) : "l"(a), "l"(b));
    return r;
}
__device__ __forceinline__ unsigned long long packx2(float lo, float hi) {
    unsigned long long r;
    asm("mov.b64 %0, {%1, %2};" : "=l"(r) : "f"(lo), "f"(hi));
    return r;
}

// ---------------- polynomial filter: acc = sum_{k=0..3} S^k x ----------------
// One CTA (1024 threads) per (graph, 32-col slice). Quarter-warp (8 lanes x float4)
// per row, 4 rows per quarter, degree-sorted assignment. Neighbor lists streamed
// from gmem via L1 (NOT smem) -> smem holds only the two u ping-pong buffers.
// nbr byte offset for row == row*PADN*2 == row*128 == u-row byte offset (roff).
#define FS 32
#define UROWS 513                        // row 512 = zero row
#define POLY_U0   0
#define POLY_U1   (POLY_U0 + UROWS*FS*4)          // +65664
#define POLY_DINV (POLY_U1 + UROWS*FS*4)          // +65664
#define POLY_PC   (POLY_DINV + NN_*4)
#define POLY_SMEM (POLY_PC + NN_*4)

__global__ void __launch_bounds__(1024, 1) poly_kernel(const float* __restrict__ xin) {
    extern __shared__ unsigned char smraw[];
    float* ubuf0   = (float*)(smraw + POLY_U0);
    float* ubuf1   = (float*)(smraw + POLY_U1);
    float* dinv_s  = (float*)(smraw + POLY_DINV);
    unsigned* pc_s = (unsigned*)(smraw + POLY_PC);

    int g  = blockIdx.y;
    int fb = blockIdx.x * FS;
    int tid = threadIdx.x, w = tid >> 5, lane = tid & 31;
    int q  = lane >> 3;            // quarter-warp id 0..3
    int li = lane & 7;             // lane in quarter; cols li*4..li*4+3
    int pbase = w * 4 + q;         // sorted position base (0..127); rows at m*128+pbase

    const char* nbr_base = (const char*)&g_nbr[(size_t)g * 512 * PADN];

    if (tid < 512) {
        dinv_s[tid] = g_dinv[g * 512 + tid];
        pc_s[tid]   = g_pc[g * 512 + tid];
    }
    // zero row 512 of both u buffers
    if (tid >= 512 && tid < 544) ubuf0[512 * FS + (tid - 512)] = 0.0f;
    else if (tid >= 544 && tid < 576) ubuf1[512 * FS + (tid - 544)] = 0.0f;
    __syncthreads();

    // per-m row metadata in registers (fixed across hops)
    int roff[4];                       // row*128 : byte offset into nbr AND u rows
    int cntm[4];
    unsigned long long ddm[4];
    unsigned long long accA[4], accB[4];

    const char* xbase = (const char*)(xin + (size_t)g * 512 * FF + fb) + li * 16;
#pragma unroll
    for (int m = 0; m < 4; m++) {
        unsigned pc = pc_s[m * 128 + pbase];
        int row = pc & 0xffffu;
        cntm[m] = pc >> 16;
        roff[m] = row * 128;
        float d = dinv_s[row];
        ddm[m] = packx2(d, d);
        ulonglong2 xv = *(const ulonglong2*)(xbase + (size_t)row * 512);
        accA[m] = xv.x; accB[m] = xv.y;
        ulonglong2 uw;
        uw.x = mulx2(ddm[m], accA[m]);
        uw.y = mulx2(ddm[m], accB[m]);
        *(ulonglong2*)((char*)ubuf0 + roff[m] + li * 16) = uw;
    }
    __syncthreads();

    float* ucur = ubuf0;
    float* unew = ubuf1;
#pragma unroll 1
    for (int hop = 0; hop < 3; hop++) {
        const char* ucb = (const char*)ucur + li * 16;   // gather base (+node*128)
#pragma unroll
        for (int m = 0; m < 4; m++) {
            const uint2* rowp = (const uint2*)(nbr_base + roff[m]);
            int cnt4 = cntm[m];
            unsigned long long sa0 = 0ull, sa1 = 0ull, sb0 = 0ull, sb1 = 0ull;
#pragma unroll 1
            for (int e = 0; e < cnt4; e += 4) {
                uint2 pk = __ldg(&rowp[e >> 2]);
                unsigned o0 = pk.x & 0xffffu, o1 = pk.x >> 16;
                unsigned o2 = pk.y & 0xffffu, o3 = pk.y >> 16;
                ulonglong2 v0 = *(const ulonglong2*)(ucb + ((size_t)o0 << 4));
                ulonglong2 v1 = *(const ulonglong2*)(ucb + ((size_t)o1 << 4));
                ulonglong2 v2 = *(const ulonglong2*)(ucb + ((size_t)o2 << 4));
                ulonglong2 v3 = *(const ulonglong2*)(ucb + ((size_t)o3 << 4));
                addx2(sa0, v0.x); addx2(sa1, v0.y);
                addx2(sb0, v1.x); addx2(sb1, v1.y);
                addx2(sa0, v2.x); addx2(sa1, v2.y);
                addx2(sb0, v3.x); addx2(sb1, v3.y);
            }
            addx2(sa0, sb0); addx2(sa1, sb1);
            unsigned long long zn0 = mulx2(ddm[m], sa0);
            unsigned long long zn1 = mulx2(ddm[m], sa1);
            addx2(accA[m], zn0); addx2(accB[m], zn1);
            if (hop < 2) {
                ulonglong2 uw;
                uw.x = mulx2(ddm[m], zn0);
                uw.y = mulx2(ddm[m], zn1);
                *(ulonglong2*)((char*)unew + roff[m] + li * 16) = uw;
            }
        }
        __syncthreads();
        float* t = ucur; ucur = unew; unew = t;
    }

    char* ybase = (char*)(g_acc + (size_t)g * 512 * FF + fb) + li * 16;
#pragma unroll
    for (int m = 0; m < 4; m++) {
        ulonglong2 ov; ov.x = accA[m]; ov.y = accB[m];
        *(ulonglong2*)(ybase + (size_t)roff[m] * 4) = ov;
    }
}

// ---------------- mma.sync GEMM + bias + relu ----------------
#define ASTR 136
#define GMM_AH 0
#define GMM_AL (GMM_AH + 128*ASTR*2)
#define GMM_BH (GMM_AL + 128*ASTR*2)
#define GMM_BL (GMM_BH + 128*ASTR*2)
#define GMM_BIAS (GMM_BL + 128*ASTR*2)
#define GEMM_MMA_SMEM (GMM_BIAS + 128*4)

__device__ __forceinline__ void mma16816(float* c, const unsigned* a, const unsigned* b) {
    asm volatile(
        "mma.sync.aligned.m16n8k16.row.col.f32.bf16.bf16.f32 "
        "{%0,%1,%2,%3}, {%4,%5,%6,%7}, {%8,%9}, {%0,%1,%2,%3};"
        : "+f"(c[0]), "+f"(c[1]), "+f"(c[2]), "+f"(c[3])
        : "r"(a[0]), "r"(a[1]), "r"(a[2]), "r"(a[3]), "r"(b[0]), "r"(b[1]));
}

__global__ void __launch_bounds__(256, 1) gemm_mma_kernel(
        const float* __restrict__ A, const unsigned int* __restrict__ wt,
        const float* __restrict__ bias, float* __restrict__ Y) {
    extern __shared__ unsigned char smg[];
    unsigned short* Ah = (unsigned short*)(smg + GMM_AH);
    unsigned short* Al = (unsigned short*)(smg + GMM_AL);
    unsigned short* Bh = (unsigned short*)(smg + GMM_BH);
    unsigned short* Bl = (unsigned short*)(smg + GMM_BL);
    float* bias_s = (float*)(smg + GMM_BIAS);

    int tid = threadIdx.x;
    int lane = tid & 31;
    int w = tid >> 5;
    int wr = w & 3;
    int wc = w >> 2;
    size_t rowbase = (size_t)blockIdx.x * 128;

    for (int idx = tid; idx < 8192; idx += 256) {
        int n = idx >> 6, p = idx & 63;
        *(unsigned int*)&Bh[n * ASTR + 2 * p] = wt[idx];
        *(unsigned int*)&Bl[n * ASTR + 2 * p] = wt[8192 + idx];
    }
    for (int idx = tid; idx < 8192; idx += 256) {
        int r = idx >> 6, p = idx & 63;
        float2 x = *(const float2*)(A + (rowbase + r) * 128 + 2 * p);
        __nv_bfloat16 h0 = __float2bfloat16(x.x);
        __nv_bfloat16 h1 = __float2bfloat16(x.y);
        __nv_bfloat16 l0 = __float2bfloat16(x.x - __bfloat162float(h0));
        __nv_bfloat16 l1 = __float2bfloat16(x.y - __bfloat162float(h1));
        *(unsigned int*)&Ah[r * ASTR + 2 * p] =
            (unsigned int)__bfloat16_as_ushort(h0) | ((unsigned int)__bfloat16_as_ushort(h1) << 16);
        *(unsigned int*)&Al[r * ASTR + 2 * p] =
            (unsigned int)__bfloat16_as_ushort(l0) | ((unsigned int)__bfloat16_as_ushort(l1) << 16);
    }
    if (tid < 128) bias_s[tid] = bias[tid];
    __syncthreads();

    float acc[2][8][4];
#pragma unroll
    for (int mt = 0; mt < 2; mt++)
#pragma unroll
        for (int nt = 0; nt < 8; nt++)
#pragma unroll
            for (int p = 0; p < 4; p++) acc[mt][nt][p] = 0.0f;

    int frow = lane >> 2;
    int fcolb = 2 * (lane & 3);

#pragma unroll
    for (int kk = 0; kk < 8; kk++) {
        int kc = fcolb + 16 * kk;
        unsigned ah[2][4], al[2][4], bh[8][2], bl[8][2];
#pragma unroll
        for (int mt = 0; mt < 2; mt++) {
            int r0 = 32 * wr + 16 * mt + frow;
            ah[mt][0] = *(const unsigned*)&Ah[r0 * ASTR + kc];
            ah[mt][1] = *(const unsigned*)&Ah[(r0 + 8) * ASTR + kc];
            ah[mt][2] = *(const unsigned*)&Ah[r0 * ASTR + kc + 8];
            ah[mt][3] = *(const unsigned*)&Ah[(r0 + 8) * ASTR + kc + 8];
            al[mt][0] = *(const unsigned*)&Al[r0 * ASTR + kc];
            al[mt][1] = *(const unsigned*)&Al[(r0 + 8) * ASTR + kc];
            al[mt][2] = *(const unsigned*)&Al[r0 * ASTR + kc + 8];
            al[mt][3] = *(const unsigned*)&Al[(r0 + 8) * ASTR + kc + 8];
        }
#pragma unroll
        for (int nt = 0; nt < 8; nt++) {
            int n0 = 64 * wc + 8 * nt + frow;
            bh[nt][0] = *(const unsigned*)&Bh[n0 * ASTR + kc];
            bh[nt][1] = *(const unsigned*)&Bh[n0 * ASTR + kc + 8];
            bl[nt][0] = *(const unsigned*)&Bl[n0 * ASTR + kc];
            bl[nt][1] = *(const unsigned*)&Bl[n0 * ASTR + kc + 8];
        }
#pragma unroll
        for (int mt = 0; mt < 2; mt++)
#pragma unroll
            for (int nt = 0; nt < 8; nt++) {
                mma16816(acc[mt][nt], ah[mt], bh[nt]);
                mma16816(acc[mt][nt], ah[mt], bl[nt]);
                mma16816(acc[mt][nt], al[mt], bh[nt]);
            }
    }

#pragma unroll
    for (int mt = 0; mt < 2; mt++) {
        size_t r0 = rowbase + 32 * wr + 16 * mt + frow;
#pragma unroll
        for (int nt = 0; nt < 8; nt++) {
            int col = 64 * wc + 8 * nt + fcolb;
            float b0 = bias_s[col], b1 = bias_s[col + 1];
            float2 v0, v1;
            float t;
            t = acc[mt][nt][0] + b0; v0.x = t > 0 ? t : 0;
            t = acc[mt][nt][1] + b1; v0.y = t > 0 ? t : 0;
            t = acc[mt][nt][2] + b0; v1.x = t > 0 ? t : 0;
            t = acc[mt][nt][3] + b1; v1.y = t > 0 ? t : 0;
            *(float2*)(Y + r0 * 128 + col)       = v0;
            *(float2*)(Y + (r0 + 8) * 128 + col) = v1;
        }
    }
}

// ---------------- head ----------------
__global__ void __launch_bounds__(512) head_kernel(
        const float* __restrict__ Wr1, const float* __restrict__ br1,
        const float* __restrict__ Wr2, const float* __restrict__ br2,
        float* __restrict__ out) {
    __shared__ float part[4][128];
    __shared__ float hs[128];
    __shared__ float rs[64];
    int g = blockIdx.x;
    int tid = threadIdx.x;
    int f = tid & 127, q = tid >> 7;

    const float* yg = g_y + (size_t)g * 512 * 128;
    float s = 0.0f;
    for (int n = q * 128; n < q * 128 + 128; n++) s += yg[(size_t)n * 128 + f];
    part[q][f] = s;
    __syncthreads();

    if (tid < 128)
        hs[tid] = (part[0][tid] + part[1][tid] + part[2][tid] + part[3][tid]) * (1.0f / 512.0f);
    __syncthreads();

    if (tid < 64) {
        float a = br1[tid];
        for (int k = 0; k < 128; k++) a += hs[k] * Wr1[k * 64 + tid];
        rs[tid] = a > 0 ? a : 0;
    }
    __syncthreads();

    if (tid == 0) {
        float a = br2[0];
        for (int o = 0; o < 64; o++) a += rs[o] * Wr2[o];
        out[g] = a;
    }
}

// ---------------- launch ----------------
extern "C" void kernel_launch(void* const* d_in, const int* in_sizes, int n_in,
                              void* d_out, int out_size) {
    const float* X   = (const float*)d_in[0];
    const int*   ei  = (const int*)d_in[2];
    const float* W1  = (const float*)d_in[3];
    const float* b1  = (const float*)d_in[4];
    const float* W2  = (const float*)d_in[5];
    const float* b2  = (const float*)d_in[6];
    const float* Wr1 = (const float*)d_in[7];
    const float* br1 = (const float*)d_in[8];
    const float* Wr2 = (const float*)d_in[9];
    const float* br2 = (const float*)d_in[10];
    float* out = (float*)d_out;

    cudaFuncSetAttribute(poly_kernel, cudaFuncAttributeMaxDynamicSharedMemorySize, POLY_SMEM);
    cudaFuncSetAttribute(gemm_mma_kernel, cudaFuncAttributeMaxDynamicSharedMemorySize, GEMM_MMA_SMEM);

    void* yaddr = nullptr;  cudaGetSymbolAddress(&yaddr, g_y);
    float* Yp = (float*)yaddr;
    void* aaddr = nullptr;  cudaGetSymbolAddress(&aaddr, g_acc);
    const float* Ap = (const float*)aaddr;
    void* w1addr = nullptr; cudaGetSymbolAddress(&w1addr, g_wt1);
    void* w2addr = nullptr; cudaGetSymbolAddress(&w2addr, g_wt2);

    // adjacency (rebuilt every call; deterministic)
    clear_adj_kernel<<<ADJ_WORDS / 256, 256>>>();
    build_adj_kernel<<<ETOT / 256, 256>>>(ei);
    expand_kernel<<<NTOT / 256, 256>>>();
    sort_kernel<<<BG, 512>>>();
    prep_w_kernel<<<64, 256>>>(W1, W2, (unsigned int*)w1addr, (unsigned int*)w2addr);

    dim3 pgrid(FF / FS, BG);

    // layer 1
    poly_kernel<<<pgrid, 1024, POLY_SMEM>>>(X);
    gemm_mma_kernel<<<NTOT / 128, 256, GEMM_MMA_SMEM>>>(Ap, (const unsigned int*)w1addr, b1, Yp);
    // layer 2
    poly_kernel<<<pgrid, 1024, POLY_SMEM>>>(Yp);
    gemm_mma_kernel<<<NTOT / 128, 256, GEMM_MMA_SMEM>>>(Ap, (const unsigned int*)w2addr, b2, Yp);
    // head
    head_kernel<<<BG, 512>>>(Wr1, br1, Wr2, br2, out);
}